// round 3
// baseline (speedup 1.0000x reference)
#include <cuda_runtime.h>
#include <cuda_bf16.h>
#include <cstdint>

// Problem constants: B=16, S=2048, D=128, fp32.
#define BATCH 16
#define SEQ   2048
#define DIM   128
#define ROWS  16       // score rows per block
#define JT    128      // j-tile width
#define NTHREADS 256
#define SPADW 2050     // padded fp32 stride for score buffer
#define KPAD  136      // padded bf16 stride for staged tiles (conflict-free frags)

// SMEM (bytes):
//   sS    : 16*2050*4        = 131200   scores -> packed split weights
//   sQhi/lo (alias sVthi/lo): 2*128*136*2 = 69632
//   sKhi/lo : 2*16*136*2     = 8704
// total 209536 <= 227KB

__device__ __forceinline__ void mma16816(float d[4], const uint32_t a[4],
                                         uint32_t b0, uint32_t b1) {
    asm volatile(
        "mma.sync.aligned.m16n8k16.row.col.f32.bf16.bf16.f32 "
        "{%0,%1,%2,%3}, {%4,%5,%6,%7}, {%8,%9}, {%0,%1,%2,%3};\n"
        : "+f"(d[0]), "+f"(d[1]), "+f"(d[2]), "+f"(d[3])
        : "r"(a[0]), "r"(a[1]), "r"(a[2]), "r"(a[3]), "r"(b0), "r"(b1));
}

__device__ __forceinline__ uint32_t b2u(__nv_bfloat162 x) {
    return *reinterpret_cast<uint32_t*>(&x);
}

__global__ void __launch_bounds__(NTHREADS, 1)
attn_mma_kernel(const float* __restrict__ Q, const float* __restrict__ K,
                const float* __restrict__ V, float* __restrict__ outO,
                float* __restrict__ outW)
{
    extern __shared__ char sm[];
    float*         sS   = (float*)sm;                          // [16][2050] f32 / packed u32
    __nv_bfloat16* sQhi = (__nv_bfloat16*)(sm + 131200);       // [128][136]
    __nv_bfloat16* sQlo = (__nv_bfloat16*)(sm + 131200 + 34816);
    __nv_bfloat16* sKhi = (__nv_bfloat16*)(sm + 200832);       // [16][136]
    __nv_bfloat16* sKlo = (__nv_bfloat16*)(sm + 205184);
    __nv_bfloat16* sVthi = sQhi;   // phase B alias: [128 d][136 j]
    __nv_bfloat16* sVtlo = sQlo;

    const int b   = blockIdx.y;
    const int i0  = blockIdx.x * ROWS;
    const int tid = threadIdx.x;
    const int w    = tid >> 5;
    const int lane = tid & 31;
    const int g = lane >> 2;      // group row / n-index
    const int q = lane & 3;       // quad col

    const float scale = 0.08838834764831845f;   // 1/sqrt(128)

    // ---- Stage K rows (scaled), split hi/lo ----
    for (int idx = tid; idx < ROWS * DIM; idx += NTHREADS) {
        int i = idx >> 7, k = idx & 127;
        float x = K[((size_t)b * SEQ + i0 + i) * DIM + k] * scale;
        __nv_bfloat16 h = __float2bfloat16_rn(x);
        __nv_bfloat16 l = __float2bfloat16_rn(x - __bfloat162float(h));
        sKhi[i * KPAD + k] = h;
        sKlo[i * KPAD + k] = l;
    }
    __syncthreads();

    // ---- Preload K A-fragments (invariant over j-tiles): 8 ksteps x 4 regs x {hi,lo}
    uint32_t aH[8][4], aL[8][4];
    #pragma unroll
    for (int ks = 0; ks < 8; ++ks) {
        int c = ks * 16 + q * 2;
        aH[ks][0] = *(const uint32_t*)(sKhi + g * KPAD + c);
        aH[ks][1] = *(const uint32_t*)(sKhi + (g + 8) * KPAD + c);
        aH[ks][2] = *(const uint32_t*)(sKhi + g * KPAD + c + 8);
        aH[ks][3] = *(const uint32_t*)(sKhi + (g + 8) * KPAD + c + 8);
        aL[ks][0] = *(const uint32_t*)(sKlo + g * KPAD + c);
        aL[ks][1] = *(const uint32_t*)(sKlo + (g + 8) * KPAD + c);
        aL[ks][2] = *(const uint32_t*)(sKlo + g * KPAD + c + 8);
        aL[ks][3] = *(const uint32_t*)(sKlo + (g + 8) * KPAD + c + 8);
    }

    const int jt0 = i0 / JT;
    const int jlo = jt0 * JT;
    const int nb  = w * 16;     // warp's 16-col slice within a tile

    // =======================  Phase A: scores = K * Q^T  =======================
    for (int jt = jt0; jt < SEQ / JT; ++jt) {
        const int j0 = jt * JT;
        // stage Q tile, split hi/lo (row j, col k layout)
        {
            const float* Qp = Q + ((size_t)b * SEQ + j0) * DIM;
            #pragma unroll
            for (int it = 0; it < 16; ++it) {
                int idx = tid + it * NTHREADS;
                int j = idx >> 5, k4 = (idx & 31) << 2;
                float4 v = *(const float4*)(Qp + j * DIM + k4);
                __nv_bfloat162 h0 = __float22bfloat162_rn(make_float2(v.x, v.y));
                __nv_bfloat162 h1 = __float22bfloat162_rn(make_float2(v.z, v.w));
                float2 f0 = __bfloat1622float2(h0), f1 = __bfloat1622float2(h1);
                __nv_bfloat162 l0 = __float22bfloat162_rn(make_float2(v.x - f0.x, v.y - f0.y));
                __nv_bfloat162 l1 = __float22bfloat162_rn(make_float2(v.z - f1.x, v.w - f1.y));
                uint2 hh; hh.x = b2u(h0); hh.y = b2u(h1);
                uint2 ll; ll.x = b2u(l0); ll.y = b2u(l1);
                *(uint2*)(sQhi + j * KPAD + k4) = hh;
                *(uint2*)(sQlo + j * KPAD + k4) = ll;
            }
        }
        __syncthreads();

        float acc0[4] = {0.f, 0.f, 0.f, 0.f};
        float acc1[4] = {0.f, 0.f, 0.f, 0.f};
        #pragma unroll
        for (int ks = 0; ks < 8; ++ks) {
            int koff = ks * 16 + q * 2;
            // ns = 0: j = nb + g
            {
                const __nv_bfloat16* ph = sQhi + (nb + g) * KPAD + koff;
                const __nv_bfloat16* pl = sQlo + (nb + g) * KPAD + koff;
                uint32_t bh0 = *(const uint32_t*)ph;
                uint32_t bh1 = *(const uint32_t*)(ph + 8);
                uint32_t bl0 = *(const uint32_t*)pl;
                uint32_t bl1 = *(const uint32_t*)(pl + 8);
                mma16816(acc0, aH[ks], bh0, bh1);
                mma16816(acc0, aH[ks], bl0, bl1);
                mma16816(acc0, aL[ks], bh0, bh1);
            }
            // ns = 1: j = nb + 8 + g
            {
                const __nv_bfloat16* ph = sQhi + (nb + 8 + g) * KPAD + koff;
                const __nv_bfloat16* pl = sQlo + (nb + 8 + g) * KPAD + koff;
                uint32_t bh0 = *(const uint32_t*)ph;
                uint32_t bh1 = *(const uint32_t*)(ph + 8);
                uint32_t bl0 = *(const uint32_t*)pl;
                uint32_t bl1 = *(const uint32_t*)(pl + 8);
                mma16816(acc1, aH[ks], bh0, bh1);
                mma16816(acc1, aH[ks], bl0, bl1);
                mma16816(acc1, aL[ks], bh0, bh1);
            }
        }

        // write scores to sS with mask (j < i -> -1e7)
        {
            const int i_r0 = i0 + g, i_r1 = i0 + g + 8;
            // ns=0 cols
            int jc = j0 + nb + q * 2;
            float2 v;
            v.x = (jc     < i_r0) ? -1.0e7f : acc0[0];
            v.y = (jc + 1 < i_r0) ? -1.0e7f : acc0[1];
            *(float2*)(sS + g * SPADW + jc) = v;
            v.x = (jc     < i_r1) ? -1.0e7f : acc0[2];
            v.y = (jc + 1 < i_r1) ? -1.0e7f : acc0[3];
            *(float2*)(sS + (g + 8) * SPADW + jc) = v;
            // ns=1 cols
            jc += 8;
            v.x = (jc     < i_r0) ? -1.0e7f : acc1[0];
            v.y = (jc + 1 < i_r0) ? -1.0e7f : acc1[1];
            *(float2*)(sS + g * SPADW + jc) = v;
            v.x = (jc     < i_r1) ? -1.0e7f : acc1[2];
            v.y = (jc + 1 < i_r1) ? -1.0e7f : acc1[3];
            *(float2*)(sS + (g + 8) * SPADW + jc) = v;
        }
        __syncthreads();
    }

    // ===============  Softmax + weights writeback + hi/lo packing  ===============
    {
        for (int r = w; r < ROWS; r += NTHREADS / 32) {
            float* row = sS + r * SPADW;
            uint32_t* rowu = (uint32_t*)row;
            float mx = -3.0e38f;
            for (int j = jlo + lane; j < SEQ; j += 32) mx = fmaxf(mx, row[j]);
            #pragma unroll
            for (int o = 16; o; o >>= 1) mx = fmaxf(mx, __shfl_xor_sync(0xffffffffu, mx, o));

            float sum = 0.f;
            for (int j = jlo + lane; j < SEQ; j += 32) {
                float e = __expf(row[j] - mx);
                row[j] = e;
                sum += e;
            }
            #pragma unroll
            for (int o = 16; o; o >>= 1) sum += __shfl_xor_sync(0xffffffffu, sum, o);
            float inv = 1.0f / sum;

            float* wrow = outW + ((size_t)b * SEQ + (i0 + r)) * SEQ;
            for (int j = lane; j < jlo; j += 32) wrow[j] = 0.0f;
            for (int j = jlo + lane; j < SEQ; j += 32) {
                float ww = row[j] * inv;
                wrow[j] = ww;
                __nv_bfloat16 h = __float2bfloat16_rn(ww);
                __nv_bfloat16 l = __float2bfloat16_rn(ww - __bfloat162float(h));
                __nv_bfloat162 p; p.x = h; p.y = l;
                rowu[j] = b2u(p);
            }
        }
    }
    __syncthreads();

    // =======================  Phase B: O = W * V  =======================
    float o0[4] = {0.f, 0.f, 0.f, 0.f};
    float o1[4] = {0.f, 0.f, 0.f, 0.f};
    const uint32_t* sSu = (const uint32_t*)sS;
    for (int jt = jt0; jt < SEQ / JT; ++jt) {
        const int j0 = jt * JT;
        // stage V tile transposed, split hi/lo: sVt[d][j]
        {
            const float* Vp = V + ((size_t)b * SEQ + j0) * DIM;
            #pragma unroll
            for (int it = 0; it < 16; ++it) {
                int idx = tid + it * NTHREADS;
                int j = idx >> 5, d4 = (idx & 31) << 2;
                float4 v = *(const float4*)(Vp + j * DIM + d4);
                #pragma unroll
                for (int m = 0; m < 4; ++m) {
                    float x = (m == 0) ? v.x : (m == 1) ? v.y : (m == 2) ? v.z : v.w;
                    __nv_bfloat16 h = __float2bfloat16_rn(x);
                    __nv_bfloat16 l = __float2bfloat16_rn(x - __bfloat162float(h));
                    sVthi[(d4 + m) * KPAD + j] = h;
                    sVtlo[(d4 + m) * KPAD + j] = l;
                }
            }
        }
        __syncthreads();

        #pragma unroll
        for (int ks = 0; ks < 8; ++ks) {
            int c = j0 + ks * 16 + q * 2;
            uint2 w00 = *(const uint2*)(sSu + g * SPADW + c);
            uint2 w10 = *(const uint2*)(sSu + (g + 8) * SPADW + c);
            uint2 w01 = *(const uint2*)(sSu + g * SPADW + c + 8);
            uint2 w11 = *(const uint2*)(sSu + (g + 8) * SPADW + c + 8);
            uint32_t aHH[4], aLL[4];
            aHH[0] = __byte_perm(w00.x, w00.y, 0x5410);
            aLL[0] = __byte_perm(w00.x, w00.y, 0x7632);
            aHH[1] = __byte_perm(w10.x, w10.y, 0x5410);
            aLL[1] = __byte_perm(w10.x, w10.y, 0x7632);
            aHH[2] = __byte_perm(w01.x, w01.y, 0x5410);
            aLL[2] = __byte_perm(w01.x, w01.y, 0x7632);
            aHH[3] = __byte_perm(w11.x, w11.y, 0x5410);
            aLL[3] = __byte_perm(w11.x, w11.y, 0x7632);

            int koff = ks * 16 + q * 2;
            // ns = 0: d = nb + g
            {
                const __nv_bfloat16* ph = sVthi + (nb + g) * KPAD + koff;
                const __nv_bfloat16* pl = sVtlo + (nb + g) * KPAD + koff;
                uint32_t bh0 = *(const uint32_t*)ph;
                uint32_t bh1 = *(const uint32_t*)(ph + 8);
                uint32_t bl0 = *(const uint32_t*)pl;
                uint32_t bl1 = *(const uint32_t*)(pl + 8);
                mma16816(o0, aHH, bh0, bh1);
                mma16816(o0, aHH, bl0, bl1);
                mma16816(o0, aLL, bh0, bh1);
            }
            // ns = 1: d = nb + 8 + g
            {
                const __nv_bfloat16* ph = sVthi + (nb + 8 + g) * KPAD + koff;
                const __nv_bfloat16* pl = sVtlo + (nb + 8 + g) * KPAD + koff;
                uint32_t bh0 = *(const uint32_t*)ph;
                uint32_t bh1 = *(const uint32_t*)(ph + 8);
                uint32_t bl0 = *(const uint32_t*)pl;
                uint32_t bl1 = *(const uint32_t*)(pl + 8);
                mma16816(o1, aHH, bh0, bh1);
                mma16816(o1, aHH, bl0, bl1);
                mma16816(o1, aLL, bh0, bh1);
            }
        }
        __syncthreads();
    }

    // ---- Write outputs ----
    {
        float* orow0 = outO + ((size_t)b * SEQ + i0 + g) * DIM;
        float* orow1 = outO + ((size_t)b * SEQ + i0 + g + 8) * DIM;
        int dc0 = nb + q * 2;
        int dc1 = nb + 8 + q * 2;
        float2 v;
        v.x = o0[0]; v.y = o0[1]; *(float2*)(orow0 + dc0) = v;
        v.x = o0[2]; v.y = o0[3]; *(float2*)(orow1 + dc0) = v;
        v.x = o1[0]; v.y = o1[1]; *(float2*)(orow0 + dc1) = v;
        v.x = o1[2]; v.y = o1[3]; *(float2*)(orow1 + dc1) = v;
    }
}

extern "C" void kernel_launch(void* const* d_in, const int* in_sizes, int n_in,
                              void* d_out, int out_size)
{
    const float* Q = (const float*)d_in[0];
    const float* K = (const float*)d_in[1];
    const float* V = (const float*)d_in[2];
    float* out  = (float*)d_out;
    float* outO = out;                               // (B,S,D)
    float* outW = out + (size_t)BATCH * SEQ * DIM;   // (B,S,S)

    const size_t smem_bytes = 209536;

    cudaFuncSetAttribute(attn_mma_kernel,
                         cudaFuncAttributeMaxDynamicSharedMemorySize,
                         (int)smem_bytes);

    dim3 grid(SEQ / ROWS, BATCH);
    attn_mma_kernel<<<grid, NTHREADS, smem_bytes>>>(Q, K, V, outO, outW);
}

// round 4
// speedup vs baseline: 3.7971x; 3.7971x over previous
#include <cuda_runtime.h>
#include <cuda_bf16.h>
#include <cstdint>

#define BATCH 16
#define SEQ   2048
#define DIM   128
#define NT    256
#define KPAD  136   // bf16 row stride for 128-wide tiles (conflict-free ldmatrix)
#define VPAD  72    // bf16 row stride for 64-wide V tiles

// Scratch: raw exp(scores) + per-row sums. __device__ globals (no allocs allowed).
__device__ float g_rowsum[BATCH * SEQ];
__device__ float g_E[(size_t)BATCH * SEQ * SEQ];

__device__ __forceinline__ void mma16816(float d[4], const uint32_t a[4],
                                         uint32_t b0, uint32_t b1) {
    asm volatile(
        "mma.sync.aligned.m16n8k16.row.col.f32.bf16.bf16.f32 "
        "{%0,%1,%2,%3}, {%4,%5,%6,%7}, {%8,%9}, {%0,%1,%2,%3};\n"
        : "+f"(d[0]), "+f"(d[1]), "+f"(d[2]), "+f"(d[3])
        : "r"(a[0]), "r"(a[1]), "r"(a[2]), "r"(a[3]), "r"(b0), "r"(b1));
}

__device__ __forceinline__ void ldsm4(uint32_t* r, uint32_t addr) {
    asm volatile("ldmatrix.sync.aligned.m8n8.x4.shared.b16 {%0,%1,%2,%3}, [%4];\n"
                 : "=r"(r[0]), "=r"(r[1]), "=r"(r[2]), "=r"(r[3]) : "r"(addr));
}
__device__ __forceinline__ void ldsm4t(uint32_t* r, uint32_t addr) {
    asm volatile("ldmatrix.sync.aligned.m8n8.x4.trans.shared.b16 {%0,%1,%2,%3}, [%4];\n"
                 : "=r"(r[0]), "=r"(r[1]), "=r"(r[2]), "=r"(r[3]) : "r"(addr));
}

__device__ __forceinline__ uint32_t bits(__nv_bfloat162 x) {
    return *reinterpret_cast<uint32_t*>(&x);
}

// fp32x4 -> bf16 hi quad + bf16 lo quad
__device__ __forceinline__ void split4(float4 v, uint2& hi, uint2& lo) {
    __nv_bfloat162 h0 = __float22bfloat162_rn(make_float2(v.x, v.y));
    __nv_bfloat162 h1 = __float22bfloat162_rn(make_float2(v.z, v.w));
    float2 f0 = __bfloat1622float2(h0), f1 = __bfloat1622float2(h1);
    __nv_bfloat162 l0 = __float22bfloat162_rn(make_float2(v.x - f0.x, v.y - f0.y));
    __nv_bfloat162 l1 = __float22bfloat162_rn(make_float2(v.z - f1.x, v.w - f1.y));
    hi.x = bits(h0); hi.y = bits(h1);
    lo.x = bits(l0); lo.y = bits(l1);
}

__global__ void zero_rowsum_kernel() {
    int i = blockIdx.x * 256 + threadIdx.x;
    if (i < BATCH * SEQ) g_rowsum[i] = 0.0f;
}

// ============================================================================
// Kernel 1: E = exp(mask(K*Q^T/sqrt(d))), tile 128x128x128, + row sums.
// Masked tiles (jt < it) just zero-fill the weights output.
// smem: sKhi/lo, sQhi/lo [128][136] bf16 each + srow[128] = 139776 B
// ============================================================================
__global__ void __launch_bounds__(NT, 1)
scores_kernel(const float* __restrict__ Q, const float* __restrict__ K,
              float* __restrict__ outW)
{
    extern __shared__ char sm1[];
    __nv_bfloat16* sKhi = (__nv_bfloat16*)(sm1);
    __nv_bfloat16* sKlo = (__nv_bfloat16*)(sm1 + 34816);
    __nv_bfloat16* sQhi = (__nv_bfloat16*)(sm1 + 69632);
    __nv_bfloat16* sQlo = (__nv_bfloat16*)(sm1 + 104448);
    float*         srow = (float*)(sm1 + 139264);

    const int jt = blockIdx.x, it = blockIdx.y, b = blockIdx.z;
    const int i0 = it * 128, j0 = jt * 128;
    const int tid = threadIdx.x;

    if (jt < it) {   // fully-masked tile: weights are exactly 0
        float4 z = make_float4(0.f, 0.f, 0.f, 0.f);
        float* Wp = outW + ((size_t)b * SEQ + i0) * SEQ + j0;
        #pragma unroll
        for (int i = 0; i < 16; ++i) {
            int idx = tid + i * NT;
            int row = idx >> 5, c4 = (idx & 31) * 4;
            *(float4*)(Wp + (size_t)row * SEQ + c4) = z;
        }
        return;
    }

    if (tid < 128) srow[tid] = 0.0f;

    const float scale = 0.08838834764831845f;   // 1/sqrt(128)
    {
        const float* Kp = K + ((size_t)b * SEQ + i0) * DIM;
        const float* Qp = Q + ((size_t)b * SEQ + j0) * DIM;
        #pragma unroll
        for (int i = 0; i < 16; ++i) {
            int idx = tid + i * NT;
            int row = idx >> 5, c4 = (idx & 31) * 4;
            float4 v = *(const float4*)(Kp + row * DIM + c4);
            v.x *= scale; v.y *= scale; v.z *= scale; v.w *= scale;
            uint2 hi, lo; split4(v, hi, lo);
            *(uint2*)(sKhi + row * KPAD + c4) = hi;
            *(uint2*)(sKlo + row * KPAD + c4) = lo;
            float4 u = *(const float4*)(Qp + row * DIM + c4);
            split4(u, hi, lo);
            *(uint2*)(sQhi + row * KPAD + c4) = hi;
            *(uint2*)(sQlo + row * KPAD + c4) = lo;
        }
    }
    __syncthreads();

    const int w = tid >> 5, lane = tid & 31;
    const int mw = w >> 2, nw = w & 3;
    const int rb = mw * 64, cb = nw * 32;

    // ldmatrix lane address offsets
    const int laneAr = lane & 15;                 // A: row offset
    const int laneAk = (lane & 16) >> 1;          // A: k offset (elems)
    const int laneBr = (lane & 7) | ((lane & 16) >> 1);  // B: n-row offset
    const int laneBk = lane & 8;                  // B: k offset

    const uint32_t aHb = (uint32_t)__cvta_generic_to_shared(sKhi) +
                         ((rb + laneAr) * KPAD + laneAk) * 2;
    const uint32_t aLb = (uint32_t)__cvta_generic_to_shared(sKlo) +
                         ((rb + laneAr) * KPAD + laneAk) * 2;
    const uint32_t bHb = (uint32_t)__cvta_generic_to_shared(sQhi) +
                         ((cb + laneBr) * KPAD + laneBk) * 2;
    const uint32_t bLb = (uint32_t)__cvta_generic_to_shared(sQlo) +
                         ((cb + laneBr) * KPAD + laneBk) * 2;

    float acc[4][4][4];
    #pragma unroll
    for (int a = 0; a < 4; ++a)
        #pragma unroll
        for (int c = 0; c < 4; ++c)
            #pragma unroll
            for (int d = 0; d < 4; ++d) acc[a][c][d] = 0.f;

    #pragma unroll
    for (int ks = 0; ks < 8; ++ks) {
        uint32_t bh[8], bl[8];
        ldsm4(bh,     bHb + ks * 32);
        ldsm4(bh + 4, bHb + 16 * KPAD * 2 + ks * 32);
        ldsm4(bl,     bLb + ks * 32);
        ldsm4(bl + 4, bLb + 16 * KPAD * 2 + ks * 32);
        #pragma unroll
        for (int mf = 0; mf < 4; ++mf) {
            uint32_t ah[4], al[4];
            ldsm4(ah, aHb + mf * 16 * KPAD * 2 + ks * 32);
            ldsm4(al, aLb + mf * 16 * KPAD * 2 + ks * 32);
            #pragma unroll
            for (int nf = 0; nf < 4; ++nf) {
                mma16816(acc[mf][nf], ah, bh[2 * nf], bh[2 * nf + 1]);
                mma16816(acc[mf][nf], ah, bl[2 * nf], bl[2 * nf + 1]);
                mma16816(acc[mf][nf], al, bh[2 * nf], bh[2 * nf + 1]);
            }
        }
    }

    // Epilogue: e = exp(s) (0 when masked j<i), store E, accumulate row sums
    const int g = lane >> 2, q = lane & 3;
    float* Ep = g_E + (size_t)b * SEQ * SEQ;
    #pragma unroll
    for (int mf = 0; mf < 4; ++mf) {
        int r0 = i0 + rb + mf * 16 + g;
        int r1 = r0 + 8;
        float s0 = 0.f, s1 = 0.f;
        #pragma unroll
        for (int nf = 0; nf < 4; ++nf) {
            int c = j0 + cb + nf * 8 + q * 2;
            float e00 = (c     >= r0) ? __expf(acc[mf][nf][0]) : 0.f;
            float e01 = (c + 1 >= r0) ? __expf(acc[mf][nf][1]) : 0.f;
            float e10 = (c     >= r1) ? __expf(acc[mf][nf][2]) : 0.f;
            float e11 = (c + 1 >= r1) ? __expf(acc[mf][nf][3]) : 0.f;
            s0 += e00 + e01; s1 += e10 + e11;
            *(float2*)(Ep + (size_t)r0 * SEQ + c) = make_float2(e00, e01);
            *(float2*)(Ep + (size_t)r1 * SEQ + c) = make_float2(e10, e11);
        }
        s0 += __shfl_xor_sync(0xffffffffu, s0, 1);
        s0 += __shfl_xor_sync(0xffffffffu, s0, 2);
        s1 += __shfl_xor_sync(0xffffffffu, s1, 1);
        s1 += __shfl_xor_sync(0xffffffffu, s1, 2);
        if (q == 0) {
            atomicAdd(&srow[rb + mf * 16 + g],     s0);
            atomicAdd(&srow[rb + mf * 16 + g + 8], s1);
        }
    }
    __syncthreads();
    if (tid < 128) atomicAdd(&g_rowsum[b * SEQ + i0 + tid], srow[tid]);
}

// ============================================================================
// Kernel 2: W = E/rowsum (write), O = W*V. Grid (2 d-halves, 16 i-tiles, 16 b).
// smem: sWhi/lo [128][136] + sVhi/lo [128][72] + sInv[128] = 107008 B -> 2 CTA/SM
// ============================================================================
__global__ void __launch_bounds__(NT, 2)
output_kernel(const float* __restrict__ V, float* __restrict__ outO,
              float* __restrict__ outW)
{
    extern __shared__ char sm2[];
    __nv_bfloat16* sWhi = (__nv_bfloat16*)(sm2);
    __nv_bfloat16* sWlo = (__nv_bfloat16*)(sm2 + 34816);
    __nv_bfloat16* sVhi = (__nv_bfloat16*)(sm2 + 69632);
    __nv_bfloat16* sVlo = (__nv_bfloat16*)(sm2 + 88064);
    float*         sInv = (float*)(sm2 + 106496);

    const int dh = blockIdx.x, it = blockIdx.y, b = blockIdx.z;
    const int i0 = it * 128, dbase = dh * 64;
    const int tid = threadIdx.x;
    const int w = tid >> 5, lane = tid & 31;
    const int mw = w >> 1, nw = w & 1;
    const int rb = mw * 32, cb = nw * 32;

    if (tid < 128) sInv[tid] = 1.0f / g_rowsum[b * SEQ + i0 + tid];
    __syncthreads();

    const int laneAr = lane & 15;
    const int laneAk = (lane & 16) >> 1;
    const int laneTr = lane & 15;                 // trans: j-row offset
    const int laneTd = (lane & 16) >> 1;          // trans: d-col offset

    const uint32_t aHb = (uint32_t)__cvta_generic_to_shared(sWhi) +
                         ((rb + laneAr) * KPAD + laneAk) * 2;
    const uint32_t aLb = (uint32_t)__cvta_generic_to_shared(sWlo) +
                         ((rb + laneAr) * KPAD + laneAk) * 2;
    const uint32_t bHb = (uint32_t)__cvta_generic_to_shared(sVhi) +
                         (laneTr * VPAD + cb + laneTd) * 2;
    const uint32_t bLb = (uint32_t)__cvta_generic_to_shared(sVlo) +
                         (laneTr * VPAD + cb + laneTd) * 2;

    float acc[2][4][4];
    #pragma unroll
    for (int a = 0; a < 2; ++a)
        #pragma unroll
        for (int c = 0; c < 4; ++c)
            #pragma unroll
            for (int d = 0; d < 4; ++d) acc[a][c][d] = 0.f;

    const float* Ep = g_E + (size_t)b * SEQ * SEQ;
    float* Wp = outW + (size_t)b * SEQ * SEQ;

    for (int jt = it; jt < 16; ++jt) {
        const int j0 = jt * 128;
        // stage normalized weights (and write them out once, from dh==0)
        #pragma unroll
        for (int i = 0; i < 16; ++i) {
            int idx = tid + i * NT;
            int row = idx >> 5, c4 = (idx & 31) * 4;
            float4 v = *(const float4*)(Ep + (size_t)(i0 + row) * SEQ + j0 + c4);
            float inv = sInv[row];
            v.x *= inv; v.y *= inv; v.z *= inv; v.w *= inv;
            if (dh == 0)
                *(float4*)(Wp + (size_t)(i0 + row) * SEQ + j0 + c4) = v;
            uint2 hi, lo; split4(v, hi, lo);
            *(uint2*)(sWhi + row * KPAD + c4) = hi;
            *(uint2*)(sWlo + row * KPAD + c4) = lo;
        }
        // stage V tile [128 j][64 d] (natural layout; ldmatrix.trans for B)
        {
            const float* Vp = V + ((size_t)b * SEQ + j0) * DIM + dbase;
            #pragma unroll
            for (int i = 0; i < 8; ++i) {
                int idx = tid + i * NT;
                int row = idx >> 4, c4 = (idx & 15) * 4;
                float4 v = *(const float4*)(Vp + row * DIM + c4);
                uint2 hi, lo; split4(v, hi, lo);
                *(uint2*)(sVhi + row * VPAD + c4) = hi;
                *(uint2*)(sVlo + row * VPAD + c4) = lo;
            }
        }
        __syncthreads();

        #pragma unroll
        for (int ks = 0; ks < 8; ++ks) {
            uint32_t bh[8], bl[8];
            ldsm4t(bh,     bHb + ks * 16 * VPAD * 2);
            ldsm4t(bh + 4, bHb + ks * 16 * VPAD * 2 + 32);   // d-cols +16
            ldsm4t(bl,     bLb + ks * 16 * VPAD * 2);
            ldsm4t(bl + 4, bLb + ks * 16 * VPAD * 2 + 32);
            #pragma unroll
            for (int mf = 0; mf < 2; ++mf) {
                uint32_t ah[4], al[4];
                ldsm4(ah, aHb + mf * 16 * KPAD * 2 + ks * 32);
                ldsm4(al, aLb + mf * 16 * KPAD * 2 + ks * 32);
                #pragma unroll
                for (int nf = 0; nf < 4; ++nf) {
                    mma16816(acc[mf][nf], ah, bh[2 * nf], bh[2 * nf + 1]);
                    mma16816(acc[mf][nf], ah, bl[2 * nf], bl[2 * nf + 1]);
                    mma16816(acc[mf][nf], al, bh[2 * nf], bh[2 * nf + 1]);
                }
            }
        }
        __syncthreads();
    }

    // epilogue: write O
    const int g = lane >> 2, q = lane & 3;
    #pragma unroll
    for (int mf = 0; mf < 2; ++mf) {
        int r0 = i0 + rb + mf * 16 + g;
        int r1 = r0 + 8;
        #pragma unroll
        for (int nf = 0; nf < 4; ++nf) {
            int c = dbase + cb + nf * 8 + q * 2;
            *(float2*)(outO + ((size_t)b * SEQ + r0) * DIM + c) =
                make_float2(acc[mf][nf][0], acc[mf][nf][1]);
            *(float2*)(outO + ((size_t)b * SEQ + r1) * DIM + c) =
                make_float2(acc[mf][nf][2], acc[mf][nf][3]);
        }
    }
}

extern "C" void kernel_launch(void* const* d_in, const int* in_sizes, int n_in,
                              void* d_out, int out_size)
{
    const float* Q = (const float*)d_in[0];
    const float* K = (const float*)d_in[1];
    const float* V = (const float*)d_in[2];
    float* out  = (float*)d_out;
    float* outO = out;                               // (B,S,D)
    float* outW = out + (size_t)BATCH * SEQ * DIM;   // (B,S,S)

    static int attr_done = 0;
    if (!attr_done) {
        cudaFuncSetAttribute(scores_kernel,
                             cudaFuncAttributeMaxDynamicSharedMemorySize, 139776);
        cudaFuncSetAttribute(output_kernel,
                             cudaFuncAttributeMaxDynamicSharedMemorySize, 107008);
        attr_done = 1;
    }

    zero_rowsum_kernel<<<BATCH * SEQ / 256, 256>>>();
    scores_kernel<<<dim3(16, 16, 16), NT, 139776>>>(Q, K, outW);
    output_kernel<<<dim3(2, 16, 16), NT, 107008>>>(V, outO, outW);
}

// round 6
// speedup vs baseline: 4.3571x; 1.1475x over previous
#include <cuda_runtime.h>
#include <cuda_bf16.h>
#include <cstdint>

#define BATCH 16
#define SEQ   2048
#define DIM   128
#define NT    256
#define KPAD  136   // bf16 row stride for 128-wide tiles (conflict-free ldmatrix)
#define VPAD  72    // bf16 row stride for 64-wide V tiles

// Scratch: raw exp(scores) + per-row sums. __device__ globals (no allocs allowed).
__device__ float g_rowsum[BATCH * SEQ];
__device__ float g_E[(size_t)BATCH * SEQ * SEQ];

__device__ __forceinline__ void mma16816(float d[4], const uint32_t a[4],
                                         uint32_t b0, uint32_t b1) {
    asm volatile(
        "mma.sync.aligned.m16n8k16.row.col.f32.bf16.bf16.f32 "
        "{%0,%1,%2,%3}, {%4,%5,%6,%7}, {%8,%9}, {%0,%1,%2,%3};\n"
        : "+f"(d[0]), "+f"(d[1]), "+f"(d[2]), "+f"(d[3])
        : "r"(a[0]), "r"(a[1]), "r"(a[2]), "r"(a[3]), "r"(b0), "r"(b1));
}

__device__ __forceinline__ void ldsm4(uint32_t* r, uint32_t addr) {
    asm volatile("ldmatrix.sync.aligned.m8n8.x4.shared.b16 {%0,%1,%2,%3}, [%4];\n"
                 : "=r"(r[0]), "=r"(r[1]), "=r"(r[2]), "=r"(r[3]) : "r"(addr));
}
__device__ __forceinline__ void ldsm4t(uint32_t* r, uint32_t addr) {
    asm volatile("ldmatrix.sync.aligned.m8n8.x4.trans.shared.b16 {%0,%1,%2,%3}, [%4];\n"
                 : "=r"(r[0]), "=r"(r[1]), "=r"(r[2]), "=r"(r[3]) : "r"(addr));
}

__device__ __forceinline__ uint32_t bits(__nv_bfloat162 x) {
    return *reinterpret_cast<uint32_t*>(&x);
}

// fp32x4 -> bf16 hi quad + bf16 lo quad
__device__ __forceinline__ void split4(float4 v, uint2& hi, uint2& lo) {
    __nv_bfloat162 h0 = __float22bfloat162_rn(make_float2(v.x, v.y));
    __nv_bfloat162 h1 = __float22bfloat162_rn(make_float2(v.z, v.w));
    float2 f0 = __bfloat1622float2(h0), f1 = __bfloat1622float2(h1);
    __nv_bfloat162 l0 = __float22bfloat162_rn(make_float2(v.x - f0.x, v.y - f0.y));
    __nv_bfloat162 l1 = __float22bfloat162_rn(make_float2(v.z - f1.x, v.w - f1.y));
    hi.x = bits(h0); hi.y = bits(h1);
    lo.x = bits(l0); lo.y = bits(l1);
}

__global__ void zero_rowsum_kernel() {
    int i = blockIdx.x * 256 + threadIdx.x;
    if (i < BATCH * SEQ) g_rowsum[i] = 0.0f;
}

// ============================================================================
// Kernel 1: E = exp(mask(K*Q^T/sqrt(d))), tile 128x128x128, + row sums.
// Masked tiles (jt < it) just zero-fill the weights output.
// smem: sKhi/lo, sQhi/lo [128][136] bf16 each + srow[128] = 139776 B
// ============================================================================
__global__ void __launch_bounds__(NT, 1)
scores_kernel(const float* __restrict__ Q, const float* __restrict__ K,
              float* __restrict__ outW)
{
    extern __shared__ char sm1[];
    __nv_bfloat16* sKhi = (__nv_bfloat16*)(sm1);
    __nv_bfloat16* sKlo = (__nv_bfloat16*)(sm1 + 34816);
    __nv_bfloat16* sQhi = (__nv_bfloat16*)(sm1 + 69632);
    __nv_bfloat16* sQlo = (__nv_bfloat16*)(sm1 + 104448);
    float*         srow = (float*)(sm1 + 139264);

    const int jt = blockIdx.x, it = blockIdx.y, b = blockIdx.z;
    const int i0 = it * 128, j0 = jt * 128;
    const int tid = threadIdx.x;

    if (jt < it) {   // fully-masked tile: weights are exactly 0
        float4 z = make_float4(0.f, 0.f, 0.f, 0.f);
        float* Wp = outW + ((size_t)b * SEQ + i0) * SEQ + j0;
        #pragma unroll
        for (int i = 0; i < 16; ++i) {
            int idx = tid + i * NT;
            int row = idx >> 5, c4 = (idx & 31) * 4;
            *(float4*)(Wp + (size_t)row * SEQ + c4) = z;
        }
        return;
    }

    if (tid < 128) srow[tid] = 0.0f;

    const float scale = 0.08838834764831845f;   // 1/sqrt(128)
    {
        const float* Kp = K + ((size_t)b * SEQ + i0) * DIM;
        const float* Qp = Q + ((size_t)b * SEQ + j0) * DIM;
        #pragma unroll
        for (int i = 0; i < 16; ++i) {
            int idx = tid + i * NT;
            int row = idx >> 5, c4 = (idx & 31) * 4;
            float4 v = *(const float4*)(Kp + row * DIM + c4);
            v.x *= scale; v.y *= scale; v.z *= scale; v.w *= scale;
            uint2 hi, lo; split4(v, hi, lo);
            *(uint2*)(sKhi + row * KPAD + c4) = hi;
            *(uint2*)(sKlo + row * KPAD + c4) = lo;
            float4 u = *(const float4*)(Qp + row * DIM + c4);
            split4(u, hi, lo);
            *(uint2*)(sQhi + row * KPAD + c4) = hi;
            *(uint2*)(sQlo + row * KPAD + c4) = lo;
        }
    }
    __syncthreads();

    const int w = tid >> 5, lane = tid & 31;
    const int mw = w >> 2, nw = w & 3;
    const int rb = mw * 64, cb = nw * 32;

    const int laneAr = lane & 15;
    const int laneAk = (lane & 16) >> 1;
    const int laneBr = (lane & 7) | ((lane & 16) >> 1);
    const int laneBk = lane & 8;

    const uint32_t aHb = (uint32_t)__cvta_generic_to_shared(sKhi) +
                         ((rb + laneAr) * KPAD + laneAk) * 2;
    const uint32_t aLb = (uint32_t)__cvta_generic_to_shared(sKlo) +
                         ((rb + laneAr) * KPAD + laneAk) * 2;
    const uint32_t bHb = (uint32_t)__cvta_generic_to_shared(sQhi) +
                         ((cb + laneBr) * KPAD + laneBk) * 2;
    const uint32_t bLb = (uint32_t)__cvta_generic_to_shared(sQlo) +
                         ((cb + laneBr) * KPAD + laneBk) * 2;

    float acc[4][4][4];
    #pragma unroll
    for (int a = 0; a < 4; ++a)
        #pragma unroll
        for (int c = 0; c < 4; ++c)
            #pragma unroll
            for (int d = 0; d < 4; ++d) acc[a][c][d] = 0.f;

    #pragma unroll
    for (int ks = 0; ks < 8; ++ks) {
        uint32_t bh[8], bl[8];
        ldsm4(bh,     bHb + ks * 32);
        ldsm4(bh + 4, bHb + 16 * KPAD * 2 + ks * 32);
        ldsm4(bl,     bLb + ks * 32);
        ldsm4(bl + 4, bLb + 16 * KPAD * 2 + ks * 32);
        #pragma unroll
        for (int mf = 0; mf < 4; ++mf) {
            uint32_t ah[4], al[4];
            ldsm4(ah, aHb + mf * 16 * KPAD * 2 + ks * 32);
            ldsm4(al, aLb + mf * 16 * KPAD * 2 + ks * 32);
            #pragma unroll
            for (int nf = 0; nf < 4; ++nf) {
                mma16816(acc[mf][nf], ah, bh[2 * nf], bh[2 * nf + 1]);
                mma16816(acc[mf][nf], ah, bl[2 * nf], bl[2 * nf + 1]);
                mma16816(acc[mf][nf], al, bh[2 * nf], bh[2 * nf + 1]);
            }
        }
    }

    // Epilogue: e = exp(s) (0 when masked j<i), store E, accumulate row sums
    const int g = lane >> 2, q = lane & 3;
    float* Ep = g_E + (size_t)b * SEQ * SEQ;
    #pragma unroll
    for (int mf = 0; mf < 4; ++mf) {
        int r0 = i0 + rb + mf * 16 + g;
        int r1 = r0 + 8;
        float s0 = 0.f, s1 = 0.f;
        #pragma unroll
        for (int nf = 0; nf < 4; ++nf) {
            int c = j0 + cb + nf * 8 + q * 2;
            float e00 = (c     >= r0) ? __expf(acc[mf][nf][0]) : 0.f;
            float e01 = (c + 1 >= r0) ? __expf(acc[mf][nf][1]) : 0.f;
            float e10 = (c     >= r1) ? __expf(acc[mf][nf][2]) : 0.f;
            float e11 = (c + 1 >= r1) ? __expf(acc[mf][nf][3]) : 0.f;
            s0 += e00 + e01; s1 += e10 + e11;
            *(float2*)(Ep + (size_t)r0 * SEQ + c) = make_float2(e00, e01);
            *(float2*)(Ep + (size_t)r1 * SEQ + c) = make_float2(e10, e11);
        }
        s0 += __shfl_xor_sync(0xffffffffu, s0, 1);
        s0 += __shfl_xor_sync(0xffffffffu, s0, 2);
        s1 += __shfl_xor_sync(0xffffffffu, s1, 1);
        s1 += __shfl_xor_sync(0xffffffffu, s1, 2);
        if (q == 0) {
            atomicAdd(&srow[rb + mf * 16 + g],     s0);
            atomicAdd(&srow[rb + mf * 16 + g + 8], s1);
        }
    }
    __syncthreads();
    if (tid < 128) atomicAdd(&g_rowsum[b * SEQ + i0 + tid], srow[tid]);
}

// ============================================================================
// Kernel 2: W = E/rowsum (write), O = W*V. Diagonal-paired for load balance:
// grid (2 d-halves, 8 pairs, 16 b); CTA processes i-tiles itp and 15-itp,
// total (16-itp) + (1+itp) = 17 j-iterations — perfectly uniform.
// smem: sWhi/lo [128][136] + sVhi/lo [128][72] + sInv[128] = 107008 B -> 2 CTA/SM
// ============================================================================
__global__ void __launch_bounds__(NT, 2)
output_kernel(const float* __restrict__ V, float* __restrict__ outO,
              float* __restrict__ outW)
{
    extern __shared__ char sm2[];
    __nv_bfloat16* sWhi = (__nv_bfloat16*)(sm2);
    __nv_bfloat16* sWlo = (__nv_bfloat16*)(sm2 + 34816);
    __nv_bfloat16* sVhi = (__nv_bfloat16*)(sm2 + 69632);
    __nv_bfloat16* sVlo = (__nv_bfloat16*)(sm2 + 88064);
    float*         sInv = (float*)(sm2 + 106496);

    const int dh = blockIdx.x, itp = blockIdx.y, b = blockIdx.z;
    const int dbase = dh * 64;
    const int tid = threadIdx.x;
    const int w = tid >> 5, lane = tid & 31;
    const int mw = w >> 1, nw = w & 1;
    const int rb = mw * 32, cb = nw * 32;

    const int laneAr = lane & 15;
    const int laneAk = (lane & 16) >> 1;
    const int laneTr = lane & 15;
    const int laneTd = (lane & 16) >> 1;

    const uint32_t aHb = (uint32_t)__cvta_generic_to_shared(sWhi) +
                         ((rb + laneAr) * KPAD + laneAk) * 2;
    const uint32_t aLb = (uint32_t)__cvta_generic_to_shared(sWlo) +
                         ((rb + laneAr) * KPAD + laneAk) * 2;
    const uint32_t bHb = (uint32_t)__cvta_generic_to_shared(sVhi) +
                         (laneTr * VPAD + cb + laneTd) * 2;
    const uint32_t bLb = (uint32_t)__cvta_generic_to_shared(sVlo) +
                         (laneTr * VPAD + cb + laneTd) * 2;

    const float* Ep = g_E + (size_t)b * SEQ * SEQ;
    float* Wp = outW + (size_t)b * SEQ * SEQ;
    const int g = lane >> 2, q = lane & 3;

    #pragma unroll 1
    for (int half = 0; half < 2; ++half) {
        const int it = (half == 0) ? itp : 15 - itp;
        const int i0 = it * 128;

        if (tid < 128) sInv[tid] = 1.0f / g_rowsum[b * SEQ + i0 + tid];
        __syncthreads();

        float acc[2][4][4];
        #pragma unroll
        for (int a = 0; a < 2; ++a)
            #pragma unroll
            for (int c = 0; c < 4; ++c)
                #pragma unroll
                for (int d = 0; d < 4; ++d) acc[a][c][d] = 0.f;

        for (int jt = it; jt < 16; ++jt) {
            const int j0 = jt * 128;
            // stage normalized weights (and write them out once, from dh==0)
            #pragma unroll
            for (int i = 0; i < 16; ++i) {
                int idx = tid + i * NT;
                int row = idx >> 5, c4 = (idx & 31) * 4;
                float4 v = *(const float4*)(Ep + (size_t)(i0 + row) * SEQ + j0 + c4);
                float inv = sInv[row];
                v.x *= inv; v.y *= inv; v.z *= inv; v.w *= inv;
                if (dh == 0)
                    *(float4*)(Wp + (size_t)(i0 + row) * SEQ + j0 + c4) = v;
                uint2 hi, lo; split4(v, hi, lo);
                *(uint2*)(sWhi + row * KPAD + c4) = hi;
                *(uint2*)(sWlo + row * KPAD + c4) = lo;
            }
            // stage V tile [128 j][64 d] (natural layout; ldmatrix.trans for B)
            {
                const float* Vp = V + ((size_t)b * SEQ + j0) * DIM + dbase;
                #pragma unroll
                for (int i = 0; i < 8; ++i) {
                    int idx = tid + i * NT;
                    int row = idx >> 4, c4 = (idx & 15) * 4;
                    float4 v = *(const float4*)(Vp + row * DIM + c4);
                    uint2 hi, lo; split4(v, hi, lo);
                    *(uint2*)(sVhi + row * VPAD + c4) = hi;
                    *(uint2*)(sVlo + row * VPAD + c4) = lo;
                }
            }
            __syncthreads();

            #pragma unroll
            for (int ks = 0; ks < 8; ++ks) {
                uint32_t bh[8], bl[8];
                ldsm4t(bh,     bHb + ks * 16 * VPAD * 2);
                ldsm4t(bh + 4, bHb + ks * 16 * VPAD * 2 + 32);   // d-cols +16
                ldsm4t(bl,     bLb + ks * 16 * VPAD * 2);
                ldsm4t(bl + 4, bLb + ks * 16 * VPAD * 2 + 32);
                #pragma unroll
                for (int mf = 0; mf < 2; ++mf) {
                    uint32_t ah[4], al[4];
                    ldsm4(ah, aHb + mf * 16 * KPAD * 2 + ks * 32);
                    ldsm4(al, aLb + mf * 16 * KPAD * 2 + ks * 32);
                    #pragma unroll
                    for (int nf = 0; nf < 4; ++nf) {
                        mma16816(acc[mf][nf], ah, bh[2 * nf], bh[2 * nf + 1]);
                        mma16816(acc[mf][nf], ah, bl[2 * nf], bl[2 * nf + 1]);
                        mma16816(acc[mf][nf], al, bh[2 * nf], bh[2 * nf + 1]);
                    }
                }
            }
            __syncthreads();
        }

        // epilogue: write O for this i-tile
        #pragma unroll
        for (int mf = 0; mf < 2; ++mf) {
            int r0 = i0 + rb + mf * 16 + g;
            int r1 = r0 + 8;
            #pragma unroll
            for (int nf = 0; nf < 4; ++nf) {
                int c = dbase + cb + nf * 8 + q * 2;
                *(float2*)(outO + ((size_t)b * SEQ + r0) * DIM + c) =
                    make_float2(acc[mf][nf][0], acc[mf][nf][1]);
                *(float2*)(outO + ((size_t)b * SEQ + r1) * DIM + c) =
                    make_float2(acc[mf][nf][2], acc[mf][nf][3]);
            }
        }
        __syncthreads();   // sInv reload safety for next half
    }
}

extern "C" void kernel_launch(void* const* d_in, const int* in_sizes, int n_in,
                              void* d_out, int out_size)
{
    const float* Q = (const float*)d_in[0];
    const float* K = (const float*)d_in[1];
    const float* V = (const float*)d_in[2];
    float* out  = (float*)d_out;
    float* outO = out;                               // (B,S,D)
    float* outW = out + (size_t)BATCH * SEQ * DIM;   // (B,S,S)

    static int attr_done = 0;
    if (!attr_done) {
        cudaFuncSetAttribute(scores_kernel,
                             cudaFuncAttributeMaxDynamicSharedMemorySize, 139776);
        cudaFuncSetAttribute(output_kernel,
                             cudaFuncAttributeMaxDynamicSharedMemorySize, 107008);
        attr_done = 1;
    }

    zero_rowsum_kernel<<<BATCH * SEQ / 256, 256>>>();
    scores_kernel<<<dim3(16, 16, 16), NT, 139776>>>(Q, K, outW);
    output_kernel<<<dim3(2, 8, 16), NT, 107008>>>(V, outO, outW);
}

// round 7
// speedup vs baseline: 4.7024x; 1.0792x over previous
#include <cuda_runtime.h>
#include <cuda_bf16.h>
#include <cstdint>

#define BATCH 16
#define SEQ   2048
#define DIM   128
#define NT    256
#define KPAD  136   // bf16 row stride for 128-wide tiles (conflict-free ldmatrix)
#define VPAD  72    // bf16 row stride for 64-wide V tiles

// Scratch: raw exp(scores) + per-row sums. __device__ globals (no allocs allowed).
__device__ float g_rowsum[BATCH * SEQ];
__device__ float g_E[(size_t)BATCH * SEQ * SEQ];

__device__ __forceinline__ void mma16816(float d[4], const uint32_t a[4],
                                         uint32_t b0, uint32_t b1) {
    asm volatile(
        "mma.sync.aligned.m16n8k16.row.col.f32.bf16.bf16.f32 "
        "{%0,%1,%2,%3}, {%4,%5,%6,%7}, {%8,%9}, {%0,%1,%2,%3};\n"
        : "+f"(d[0]), "+f"(d[1]), "+f"(d[2]), "+f"(d[3])
        : "r"(a[0]), "r"(a[1]), "r"(a[2]), "r"(a[3]), "r"(b0), "r"(b1));
}

__device__ __forceinline__ void ldsm4(uint32_t* r, uint32_t addr) {
    asm volatile("ldmatrix.sync.aligned.m8n8.x4.shared.b16 {%0,%1,%2,%3}, [%4];\n"
                 : "=r"(r[0]), "=r"(r[1]), "=r"(r[2]), "=r"(r[3]) : "r"(addr));
}
__device__ __forceinline__ void ldsm4t(uint32_t* r, uint32_t addr) {
    asm volatile("ldmatrix.sync.aligned.m8n8.x4.trans.shared.b16 {%0,%1,%2,%3}, [%4];\n"
                 : "=r"(r[0]), "=r"(r[1]), "=r"(r[2]), "=r"(r[3]) : "r"(addr));
}

__device__ __forceinline__ uint32_t bits(__nv_bfloat162 x) {
    return *reinterpret_cast<uint32_t*>(&x);
}

// fp32x4 -> bf16 hi quad + bf16 lo quad
__device__ __forceinline__ void split4(float4 v, uint2& hi, uint2& lo) {
    __nv_bfloat162 h0 = __float22bfloat162_rn(make_float2(v.x, v.y));
    __nv_bfloat162 h1 = __float22bfloat162_rn(make_float2(v.z, v.w));
    float2 f0 = __bfloat1622float2(h0), f1 = __bfloat1622float2(h1);
    __nv_bfloat162 l0 = __float22bfloat162_rn(make_float2(v.x - f0.x, v.y - f0.y));
    __nv_bfloat162 l1 = __float22bfloat162_rn(make_float2(v.z - f1.x, v.w - f1.y));
    hi.x = bits(h0); hi.y = bits(h1);
    lo.x = bits(l0); lo.y = bits(l1);
}

// ============================================================================
// Kernel 1 (strip form): per CTA, i-tile pair {itp, 15-itp}; for each i-tile,
// loop jt=it..15: E = exp(mask(K*Q^T/sqrt(d))) -> gmem, rowsums in registers.
// Also zero-fills the masked W prefix (cols [0,i0)) for its rows.
// Grid (8 pairs, 16 b) = 128 CTAs -> single wave, 17 GEMMs each.
// smem: sKhi/lo, sQhi/lo [128][136] bf16 + srow[128] = 139776 B
// ============================================================================
__global__ void __launch_bounds__(NT, 1)
scores_strip_kernel(const float* __restrict__ Q, const float* __restrict__ K,
                    float* __restrict__ outW)
{
    extern __shared__ char sm1[];
    __nv_bfloat16* sKhi = (__nv_bfloat16*)(sm1);
    __nv_bfloat16* sKlo = (__nv_bfloat16*)(sm1 + 34816);
    __nv_bfloat16* sQhi = (__nv_bfloat16*)(sm1 + 69632);
    __nv_bfloat16* sQlo = (__nv_bfloat16*)(sm1 + 104448);
    float*         srow = (float*)(sm1 + 139264);

    const int itp = blockIdx.x, b = blockIdx.y;
    const int tid = threadIdx.x;
    const int w = tid >> 5, lane = tid & 31;
    const int mw = w >> 2, nw = w & 3;
    const int rb = mw * 64, cb = nw * 32;

    const int laneAr = lane & 15;
    const int laneAk = (lane & 16) >> 1;
    const int laneBr = (lane & 7) | ((lane & 16) >> 1);
    const int laneBk = lane & 8;

    const uint32_t aHb = (uint32_t)__cvta_generic_to_shared(sKhi) +
                         ((rb + laneAr) * KPAD + laneAk) * 2;
    const uint32_t aLb = (uint32_t)__cvta_generic_to_shared(sKlo) +
                         ((rb + laneAr) * KPAD + laneAk) * 2;
    const uint32_t bHb = (uint32_t)__cvta_generic_to_shared(sQhi) +
                         ((cb + laneBr) * KPAD + laneBk) * 2;
    const uint32_t bLb = (uint32_t)__cvta_generic_to_shared(sQlo) +
                         ((cb + laneBr) * KPAD + laneBk) * 2;

    const float scale = 0.08838834764831845f;   // 1/sqrt(128)
    const int g = lane >> 2, q = lane & 3;

    #pragma unroll 1
    for (int half = 0; half < 2; ++half) {
        const int it = (half == 0) ? itp : 15 - itp;
        const int i0 = it * 128;

        // stage K tile for this strip (scaled, split)
        {
            const float* Kp = K + ((size_t)b * SEQ + i0) * DIM;
            #pragma unroll
            for (int i = 0; i < 16; ++i) {
                int idx = tid + i * NT;
                int row = idx >> 5, c4 = (idx & 31) * 4;
                float4 v = *(const float4*)(Kp + row * DIM + c4);
                v.x *= scale; v.y *= scale; v.z *= scale; v.w *= scale;
                uint2 hi, lo; split4(v, hi, lo);
                *(uint2*)(sKhi + row * KPAD + c4) = hi;
                *(uint2*)(sKlo + row * KPAD + c4) = lo;
            }
        }
        if (tid < 128) srow[tid] = 0.0f;

        // zero-fill masked W prefix: rows [i0,i0+128), cols [0,i0)
        if (i0 > 0) {
            float4 z = make_float4(0.f, 0.f, 0.f, 0.f);
            float* Wp = outW + ((size_t)b * SEQ + i0) * SEQ;
            const int c4n = i0 >> 2;
            const int total = 128 * c4n;
            for (int x = tid; x < total; x += NT) {
                int row = x / c4n, c = (x - row * c4n) * 4;
                *(float4*)(Wp + (size_t)row * SEQ + c) = z;
            }
        }
        __syncthreads();

        float rsum[8];
        #pragma unroll
        for (int k = 0; k < 8; ++k) rsum[k] = 0.f;

        float* Ep = g_E + (size_t)b * SEQ * SEQ;

        for (int jt = it; jt < 16; ++jt) {
            const int j0 = jt * 128;
            // stage Q tile (split)
            {
                const float* Qp = Q + ((size_t)b * SEQ + j0) * DIM;
                #pragma unroll
                for (int i = 0; i < 16; ++i) {
                    int idx = tid + i * NT;
                    int row = idx >> 5, c4 = (idx & 31) * 4;
                    float4 u = *(const float4*)(Qp + row * DIM + c4);
                    uint2 hi, lo; split4(u, hi, lo);
                    *(uint2*)(sQhi + row * KPAD + c4) = hi;
                    *(uint2*)(sQlo + row * KPAD + c4) = lo;
                }
            }
            __syncthreads();

            float acc[4][4][4];
            #pragma unroll
            for (int a = 0; a < 4; ++a)
                #pragma unroll
                for (int c = 0; c < 4; ++c)
                    #pragma unroll
                    for (int d = 0; d < 4; ++d) acc[a][c][d] = 0.f;

            #pragma unroll
            for (int ks = 0; ks < 8; ++ks) {
                uint32_t bh[8], bl[8];
                ldsm4(bh,     bHb + ks * 32);
                ldsm4(bh + 4, bHb + 16 * KPAD * 2 + ks * 32);
                ldsm4(bl,     bLb + ks * 32);
                ldsm4(bl + 4, bLb + 16 * KPAD * 2 + ks * 32);
                #pragma unroll
                for (int mf = 0; mf < 4; ++mf) {
                    uint32_t ah[4], al[4];
                    ldsm4(ah, aHb + mf * 16 * KPAD * 2 + ks * 32);
                    ldsm4(al, aLb + mf * 16 * KPAD * 2 + ks * 32);
                    #pragma unroll
                    for (int nf = 0; nf < 4; ++nf) {
                        mma16816(acc[mf][nf], ah, bh[2 * nf], bh[2 * nf + 1]);
                        mma16816(acc[mf][nf], ah, bl[2 * nf], bl[2 * nf + 1]);
                        mma16816(acc[mf][nf], al, bh[2 * nf], bh[2 * nf + 1]);
                    }
                }
            }

            // epilogue: exp + mask (diag tile only), store E, accumulate rowsums
            const bool diag = (jt == it);
            #pragma unroll
            for (int mf = 0; mf < 4; ++mf) {
                int r0 = i0 + rb + mf * 16 + g;
                int r1 = r0 + 8;
                float s0 = 0.f, s1 = 0.f;
                #pragma unroll
                for (int nf = 0; nf < 4; ++nf) {
                    int c = j0 + cb + nf * 8 + q * 2;
                    float e00 = __expf(acc[mf][nf][0]);
                    float e01 = __expf(acc[mf][nf][1]);
                    float e10 = __expf(acc[mf][nf][2]);
                    float e11 = __expf(acc[mf][nf][3]);
                    if (diag) {
                        if (c     < r0) e00 = 0.f;
                        if (c + 1 < r0) e01 = 0.f;
                        if (c     < r1) e10 = 0.f;
                        if (c + 1 < r1) e11 = 0.f;
                    }
                    s0 += e00 + e01; s1 += e10 + e11;
                    *(float2*)(Ep + (size_t)r0 * SEQ + c) = make_float2(e00, e01);
                    *(float2*)(Ep + (size_t)r1 * SEQ + c) = make_float2(e10, e11);
                }
                rsum[mf * 2]     += s0;
                rsum[mf * 2 + 1] += s1;
            }
            __syncthreads();   // protect sQ before next stage
        }

        // reduce rowsums: quad shuffle then one smem atomic per (warp,row)
        #pragma unroll
        for (int k = 0; k < 8; ++k) {
            float s = rsum[k];
            s += __shfl_xor_sync(0xffffffffu, s, 1);
            s += __shfl_xor_sync(0xffffffffu, s, 2);
            if (q == 0) {
                int mf = k >> 1;
                int row = rb + mf * 16 + g + (k & 1) * 8;
                atomicAdd(&srow[row], s);
            }
        }
        __syncthreads();
        if (tid < 128) g_rowsum[b * SEQ + i0 + tid] = srow[tid];
        __syncthreads();   // srow/sK reuse safety for next half
    }
}

// ============================================================================
// Kernel 2: W = E/rowsum (write), O = W*V. Diagonal-paired for load balance:
// grid (2 d-halves, 8 pairs, 16 b); CTA processes i-tiles itp and 15-itp,
// total 17 j-iterations — perfectly uniform.
// smem: sWhi/lo [128][136] + sVhi/lo [128][72] + sInv[128] = 107008 B -> 2 CTA/SM
// ============================================================================
__global__ void __launch_bounds__(NT, 2)
output_kernel(const float* __restrict__ V, float* __restrict__ outO,
              float* __restrict__ outW)
{
    extern __shared__ char sm2[];
    __nv_bfloat16* sWhi = (__nv_bfloat16*)(sm2);
    __nv_bfloat16* sWlo = (__nv_bfloat16*)(sm2 + 34816);
    __nv_bfloat16* sVhi = (__nv_bfloat16*)(sm2 + 69632);
    __nv_bfloat16* sVlo = (__nv_bfloat16*)(sm2 + 88064);
    float*         sInv = (float*)(sm2 + 106496);

    const int dh = blockIdx.x, itp = blockIdx.y, b = blockIdx.z;
    const int dbase = dh * 64;
    const int tid = threadIdx.x;
    const int w = tid >> 5, lane = tid & 31;
    const int mw = w >> 1, nw = w & 1;
    const int rb = mw * 32, cb = nw * 32;

    const int laneAr = lane & 15;
    const int laneAk = (lane & 16) >> 1;
    const int laneTr = lane & 15;
    const int laneTd = (lane & 16) >> 1;

    const uint32_t aHb = (uint32_t)__cvta_generic_to_shared(sWhi) +
                         ((rb + laneAr) * KPAD + laneAk) * 2;
    const uint32_t aLb = (uint32_t)__cvta_generic_to_shared(sWlo) +
                         ((rb + laneAr) * KPAD + laneAk) * 2;
    const uint32_t bHb = (uint32_t)__cvta_generic_to_shared(sVhi) +
                         (laneTr * VPAD + cb + laneTd) * 2;
    const uint32_t bLb = (uint32_t)__cvta_generic_to_shared(sVlo) +
                         (laneTr * VPAD + cb + laneTd) * 2;

    const float* Ep = g_E + (size_t)b * SEQ * SEQ;
    float* Wp = outW + (size_t)b * SEQ * SEQ;
    const int g = lane >> 2, q = lane & 3;

    #pragma unroll 1
    for (int half = 0; half < 2; ++half) {
        const int it = (half == 0) ? itp : 15 - itp;
        const int i0 = it * 128;

        if (tid < 128) sInv[tid] = 1.0f / g_rowsum[b * SEQ + i0 + tid];
        __syncthreads();

        float acc[2][4][4];
        #pragma unroll
        for (int a = 0; a < 2; ++a)
            #pragma unroll
            for (int c = 0; c < 4; ++c)
                #pragma unroll
                for (int d = 0; d < 4; ++d) acc[a][c][d] = 0.f;

        for (int jt = it; jt < 16; ++jt) {
            const int j0 = jt * 128;
            // stage normalized weights (and write them out once, from dh==0)
            #pragma unroll
            for (int i = 0; i < 16; ++i) {
                int idx = tid + i * NT;
                int row = idx >> 5, c4 = (idx & 31) * 4;
                float4 v = *(const float4*)(Ep + (size_t)(i0 + row) * SEQ + j0 + c4);
                float inv = sInv[row];
                v.x *= inv; v.y *= inv; v.z *= inv; v.w *= inv;
                if (dh == 0)
                    *(float4*)(Wp + (size_t)(i0 + row) * SEQ + j0 + c4) = v;
                uint2 hi, lo; split4(v, hi, lo);
                *(uint2*)(sWhi + row * KPAD + c4) = hi;
                *(uint2*)(sWlo + row * KPAD + c4) = lo;
            }
            // stage V tile [128 j][64 d] (natural layout; ldmatrix.trans for B)
            {
                const float* Vp = V + ((size_t)b * SEQ + j0) * DIM + dbase;
                #pragma unroll
                for (int i = 0; i < 8; ++i) {
                    int idx = tid + i * NT;
                    int row = idx >> 4, c4 = (idx & 15) * 4;
                    float4 v = *(const float4*)(Vp + row * DIM + c4);
                    uint2 hi, lo; split4(v, hi, lo);
                    *(uint2*)(sVhi + row * VPAD + c4) = hi;
                    *(uint2*)(sVlo + row * VPAD + c4) = lo;
                }
            }
            __syncthreads();

            #pragma unroll
            for (int ks = 0; ks < 8; ++ks) {
                uint32_t bh[8], bl[8];
                ldsm4t(bh,     bHb + ks * 16 * VPAD * 2);
                ldsm4t(bh + 4, bHb + ks * 16 * VPAD * 2 + 32);   // d-cols +16
                ldsm4t(bl,     bLb + ks * 16 * VPAD * 2);
                ldsm4t(bl + 4, bLb + ks * 16 * VPAD * 2 + 32);
                #pragma unroll
                for (int mf = 0; mf < 2; ++mf) {
                    uint32_t ah[4], al[4];
                    ldsm4(ah, aHb + mf * 16 * KPAD * 2 + ks * 32);
                    ldsm4(al, aLb + mf * 16 * KPAD * 2 + ks * 32);
                    #pragma unroll
                    for (int nf = 0; nf < 4; ++nf) {
                        mma16816(acc[mf][nf], ah, bh[2 * nf], bh[2 * nf + 1]);
                        mma16816(acc[mf][nf], ah, bl[2 * nf], bl[2 * nf + 1]);
                        mma16816(acc[mf][nf], al, bh[2 * nf], bh[2 * nf + 1]);
                    }
                }
            }
            __syncthreads();
        }

        // epilogue: write O for this i-tile
        #pragma unroll
        for (int mf = 0; mf < 2; ++mf) {
            int r0 = i0 + rb + mf * 16 + g;
            int r1 = r0 + 8;
            #pragma unroll
            for (int nf = 0; nf < 4; ++nf) {
                int c = dbase + cb + nf * 8 + q * 2;
                *(float2*)(outO + ((size_t)b * SEQ + r0) * DIM + c) =
                    make_float2(acc[mf][nf][0], acc[mf][nf][1]);
                *(float2*)(outO + ((size_t)b * SEQ + r1) * DIM + c) =
                    make_float2(acc[mf][nf][2], acc[mf][nf][3]);
            }
        }
        __syncthreads();   // sInv reload safety for next half
    }
}

extern "C" void kernel_launch(void* const* d_in, const int* in_sizes, int n_in,
                              void* d_out, int out_size)
{
    const float* Q = (const float*)d_in[0];
    const float* K = (const float*)d_in[1];
    const float* V = (const float*)d_in[2];
    float* out  = (float*)d_out;
    float* outO = out;                               // (B,S,D)
    float* outW = out + (size_t)BATCH * SEQ * DIM;   // (B,S,S)

    static int attr_done = 0;
    if (!attr_done) {
        cudaFuncSetAttribute(scores_strip_kernel,
                             cudaFuncAttributeMaxDynamicSharedMemorySize, 139776);
        cudaFuncSetAttribute(output_kernel,
                             cudaFuncAttributeMaxDynamicSharedMemorySize, 107008);
        attr_done = 1;
    }

    scores_strip_kernel<<<dim3(8, 16), NT, 139776>>>(Q, K, outW);
    output_kernel<<<dim3(2, 8, 16), NT, 107008>>>(V, outO, outW);
}

// round 10
// speedup vs baseline: 6.0620x; 1.2891x over previous
#include <cuda_runtime.h>
#include <cuda_bf16.h>
#include <cstdint>

#define BATCH 16
#define SEQ   2048
#define DIM   128
#define NT    256
#define KPAD  136   // bf16 row stride for 128-wide tiles (conflict-free ldmatrix)

// Scratch: raw exp(scores) + per-row sums. __device__ globals (no allocs allowed).
__device__ float g_rowsum[BATCH * SEQ];
__device__ float g_E[(size_t)BATCH * SEQ * SEQ];

__device__ __forceinline__ void mma16816(float d[4], const uint32_t a[4],
                                         uint32_t b0, uint32_t b1) {
    asm volatile(
        "mma.sync.aligned.m16n8k16.row.col.f32.bf16.bf16.f32 "
        "{%0,%1,%2,%3}, {%4,%5,%6,%7}, {%8,%9}, {%0,%1,%2,%3};\n"
        : "+f"(d[0]), "+f"(d[1]), "+f"(d[2]), "+f"(d[3])
        : "r"(a[0]), "r"(a[1]), "r"(a[2]), "r"(a[3]), "r"(b0), "r"(b1));
}

__device__ __forceinline__ void ldsm4(uint32_t* r, uint32_t addr) {
    asm volatile("ldmatrix.sync.aligned.m8n8.x4.shared.b16 {%0,%1,%2,%3}, [%4];\n"
                 : "=r"(r[0]), "=r"(r[1]), "=r"(r[2]), "=r"(r[3]) : "r"(addr));
}
__device__ __forceinline__ void ldsm4t(uint32_t* r, uint32_t addr) {
    asm volatile("ldmatrix.sync.aligned.m8n8.x4.trans.shared.b16 {%0,%1,%2,%3}, [%4];\n"
                 : "=r"(r[0]), "=r"(r[1]), "=r"(r[2]), "=r"(r[3]) : "r"(addr));
}

__device__ __forceinline__ uint32_t bits(__nv_bfloat162 x) {
    return *reinterpret_cast<uint32_t*>(&x);
}

// fp32x4 -> bf16 hi quad + bf16 lo quad
__device__ __forceinline__ void split4(float4 v, uint2& hi, uint2& lo) {
    __nv_bfloat162 h0 = __float22bfloat162_rn(make_float2(v.x, v.y));
    __nv_bfloat162 h1 = __float22bfloat162_rn(make_float2(v.z, v.w));
    float2 f0 = __bfloat1622float2(h0), f1 = __bfloat1622float2(h1);
    __nv_bfloat162 l0 = __float22bfloat162_rn(make_float2(v.x - f0.x, v.y - f0.y));
    __nv_bfloat162 l1 = __float22bfloat162_rn(make_float2(v.z - f1.x, v.w - f1.y));
    hi.x = bits(h0); hi.y = bits(h1);
    lo.x = bits(l0); lo.y = bits(l1);
}

// ============================================================================
// Kernel 1 (strip form): per CTA, i-tile pair {itp, 15-itp}; for each i-tile,
// loop jt=it..15: E = exp(mask(K*Q^T/sqrt(d))) -> gmem, rowsums in registers.
// Next-Q half-tile register prefetch overlaps LDG with MMA.
// Grid (8 pairs, 16 b) = 128 CTAs -> single wave, 17 GEMMs each.
// smem: sKhi/lo, sQhi/lo [128][136] bf16 + srow[128] = 139776 B
// ============================================================================
__global__ void __launch_bounds__(NT, 1)
scores_strip_kernel(const float* __restrict__ Q, const float* __restrict__ K,
                    float* __restrict__ outW)
{
    extern __shared__ char sm1[];
    __nv_bfloat16* sKhi = (__nv_bfloat16*)(sm1);
    __nv_bfloat16* sKlo = (__nv_bfloat16*)(sm1 + 34816);
    __nv_bfloat16* sQhi = (__nv_bfloat16*)(sm1 + 69632);
    __nv_bfloat16* sQlo = (__nv_bfloat16*)(sm1 + 104448);
    float*         srow = (float*)(sm1 + 139264);

    const int itp = blockIdx.x, b = blockIdx.y;
    const int tid = threadIdx.x;
    const int w = tid >> 5, lane = tid & 31;
    const int mw = w >> 2, nw = w & 3;
    const int rb = mw * 64, cb = nw * 32;

    const int laneAr = lane & 15;
    const int laneAk = (lane & 16) >> 1;
    const int laneBr = (lane & 7) | ((lane & 16) >> 1);
    const int laneBk = lane & 8;

    const uint32_t aHb = (uint32_t)__cvta_generic_to_shared(sKhi) +
                         ((rb + laneAr) * KPAD + laneAk) * 2;
    const uint32_t aLb = (uint32_t)__cvta_generic_to_shared(sKlo) +
                         ((rb + laneAr) * KPAD + laneAk) * 2;
    const uint32_t bHb = (uint32_t)__cvta_generic_to_shared(sQhi) +
                         ((cb + laneBr) * KPAD + laneBk) * 2;
    const uint32_t bLb = (uint32_t)__cvta_generic_to_shared(sQlo) +
                         ((cb + laneBr) * KPAD + laneBk) * 2;

    const float scale = 0.08838834764831845f;   // 1/sqrt(128)
    const int g = lane >> 2, q = lane & 3;

    // per-thread staging coordinates (row, col4) for idx = tid + i*NT
    const int prow = tid >> 5;           // rows covered: prow + i*8
    const int pc4  = (tid & 31) * 4;

    #pragma unroll 1
    for (int half = 0; half < 2; ++half) {
        const int it = (half == 0) ? itp : 15 - itp;
        const int i0 = it * 128;
        const float* Qbase = Q + (size_t)b * SEQ * DIM;

        // stage K tile for this strip (scaled, split)
        {
            const float* Kp = K + ((size_t)b * SEQ + i0) * DIM;
            #pragma unroll
            for (int i = 0; i < 16; ++i) {
                int row = prow + i * 8;
                float4 v = *(const float4*)(Kp + row * DIM + pc4);
                v.x *= scale; v.y *= scale; v.z *= scale; v.w *= scale;
                uint2 hi, lo; split4(v, hi, lo);
                *(uint2*)(sKhi + row * KPAD + pc4) = hi;
                *(uint2*)(sKlo + row * KPAD + pc4) = lo;
            }
        }
        if (tid < 128) srow[tid] = 0.0f;

        // zero-fill masked W prefix: rows [i0,i0+128), cols [0,i0)
        if (i0 > 0) {
            float4 z = make_float4(0.f, 0.f, 0.f, 0.f);
            float* Wp = outW + ((size_t)b * SEQ + i0) * SEQ;
            const int c4n = i0 >> 2;
            const int total = 128 * c4n;
            for (int x = tid; x < total; x += NT) {
                int row = x / c4n, c = (x - row * c4n) * 4;
                *(float4*)(Wp + (size_t)row * SEQ + c) = z;
            }
        }

        float rsum[8];
        #pragma unroll
        for (int k = 0; k < 8; ++k) rsum[k] = 0.f;

        float* Ep = g_E + (size_t)b * SEQ * SEQ;

        // prefetch first Q half-tile (rows 0..63) into registers
        float4 qpre[8];
        #pragma unroll
        for (int i = 0; i < 8; ++i)
            qpre[i] = *(const float4*)(Qbase + (it * 128 + prow + i * 8) * DIM + pc4);

        for (int jt = it; jt < 16; ++jt) {
            const int j0 = jt * 128;
            // stage Q tile: rows 0..63 from prefetch regs, 64..127 direct
            {
                const float* Qp = Qbase + (size_t)j0 * DIM;
                #pragma unroll
                for (int i = 0; i < 8; ++i) {
                    int row = prow + i * 8;
                    uint2 hi, lo; split4(qpre[i], hi, lo);
                    *(uint2*)(sQhi + row * KPAD + pc4) = hi;
                    *(uint2*)(sQlo + row * KPAD + pc4) = lo;
                }
                #pragma unroll
                for (int i = 8; i < 16; ++i) {
                    int row = prow + i * 8;
                    float4 u = *(const float4*)(Qp + row * DIM + pc4);
                    uint2 hi, lo; split4(u, hi, lo);
                    *(uint2*)(sQhi + row * KPAD + pc4) = hi;
                    *(uint2*)(sQlo + row * KPAD + pc4) = lo;
                }
            }
            __syncthreads();

            // prefetch next Q half-tile: overlaps with MMA below
            if (jt + 1 < 16) {
                const float* Qn = Qbase + (size_t)(j0 + 128) * DIM;
                #pragma unroll
                for (int i = 0; i < 8; ++i)
                    qpre[i] = *(const float4*)(Qn + (prow + i * 8) * DIM + pc4);
            }

            float acc[4][4][4];
            #pragma unroll
            for (int a = 0; a < 4; ++a)
                #pragma unroll
                for (int c = 0; c < 4; ++c)
                    #pragma unroll
                    for (int d = 0; d < 4; ++d) acc[a][c][d] = 0.f;

            #pragma unroll
            for (int ks = 0; ks < 8; ++ks) {
                uint32_t bh[8], bl[8];
                ldsm4(bh,     bHb + ks * 32);
                ldsm4(bh + 4, bHb + 16 * KPAD * 2 + ks * 32);
                ldsm4(bl,     bLb + ks * 32);
                ldsm4(bl + 4, bLb + 16 * KPAD * 2 + ks * 32);
                #pragma unroll
                for (int mf = 0; mf < 4; ++mf) {
                    uint32_t ah[4], al[4];
                    ldsm4(ah, aHb + mf * 16 * KPAD * 2 + ks * 32);
                    ldsm4(al, aLb + mf * 16 * KPAD * 2 + ks * 32);
                    #pragma unroll
                    for (int nf = 0; nf < 4; ++nf) {
                        mma16816(acc[mf][nf], ah, bh[2 * nf], bh[2 * nf + 1]);
                        mma16816(acc[mf][nf], ah, bl[2 * nf], bl[2 * nf + 1]);
                        mma16816(acc[mf][nf], al, bh[2 * nf], bh[2 * nf + 1]);
                    }
                }
            }

            // epilogue: exp + mask (diag tile only), store E, accumulate rowsums
            const bool diag = (jt == it);
            #pragma unroll
            for (int mf = 0; mf < 4; ++mf) {
                int r0 = i0 + rb + mf * 16 + g;
                int r1 = r0 + 8;
                float s0 = 0.f, s1 = 0.f;
                #pragma unroll
                for (int nf = 0; nf < 4; ++nf) {
                    int c = j0 + cb + nf * 8 + q * 2;
                    float e00 = __expf(acc[mf][nf][0]);
                    float e01 = __expf(acc[mf][nf][1]);
                    float e10 = __expf(acc[mf][nf][2]);
                    float e11 = __expf(acc[mf][nf][3]);
                    if (diag) {
                        if (c     < r0) e00 = 0.f;
                        if (c + 1 < r0) e01 = 0.f;
                        if (c     < r1) e10 = 0.f;
                        if (c + 1 < r1) e11 = 0.f;
                    }
                    s0 += e00 + e01; s1 += e10 + e11;
                    *(float2*)(Ep + (size_t)r0 * SEQ + c) = make_float2(e00, e01);
                    *(float2*)(Ep + (size_t)r1 * SEQ + c) = make_float2(e10, e11);
                }
                rsum[mf * 2]     += s0;
                rsum[mf * 2 + 1] += s1;
            }
            __syncthreads();   // protect sQ before next stage
        }

        // reduce rowsums: quad shuffle then one smem atomic per (warp,row)
        #pragma unroll
        for (int k = 0; k < 8; ++k) {
            float s = rsum[k];
            s += __shfl_xor_sync(0xffffffffu, s, 1);
            s += __shfl_xor_sync(0xffffffffu, s, 2);
            if (q == 0) {
                int mf = k >> 1;
                int row = rb + mf * 16 + g + (k & 1) * 8;
                atomicAdd(&srow[row], s);
            }
        }
        __syncthreads();
        if (tid < 128) g_rowsum[b * SEQ + i0 + tid] = srow[tid];
        __syncthreads();   // srow/sK reuse safety for next half
    }
}

// ============================================================================
// Kernel 2: W = E/rowsum (write), O = W*V. Row-split (64 i-rows x full D=128
// per CTA) so E read/normalize/split/W-write are NOT duplicated; only V
// staging is shared. Diagonal-paired; grid (2 row-halves, 8 pairs, 16 b)
// = 256 CTAs, 17 uniform j-iterations each.
// smem: sWhi/lo [64][136] + sVhi/lo [128][136] + sInv[64] = 104704 B -> 2 CTA/SM
// ============================================================================
__global__ void __launch_bounds__(NT, 2)
output_kernel(const float* __restrict__ V, float* __restrict__ outO,
              float* __restrict__ outW)
{
    extern __shared__ char sm2[];
    __nv_bfloat16* sWhi = (__nv_bfloat16*)(sm2);
    __nv_bfloat16* sWlo = (__nv_bfloat16*)(sm2 + 17408);
    __nv_bfloat16* sVhi = (__nv_bfloat16*)(sm2 + 34816);
    __nv_bfloat16* sVlo = (__nv_bfloat16*)(sm2 + 69632);
    float*         sInv = (float*)(sm2 + 104448);

    const int rh = blockIdx.x, itp = blockIdx.y, b = blockIdx.z;
    const int tid = threadIdx.x;
    const int w = tid >> 5, lane = tid & 31;
    const int mw = w >> 2, nw = w & 3;
    const int rb = mw * 32, cb = nw * 32;   // 64 rows, 128 d-cols per CTA

    const int laneAr = lane & 15;
    const int laneAk = (lane & 16) >> 1;
    const int laneTr = lane & 15;
    const int laneTd = (lane & 16) >> 1;

    const uint32_t aHb = (uint32_t)__cvta_generic_to_shared(sWhi) +
                         ((rb + laneAr) * KPAD + laneAk) * 2;
    const uint32_t aLb = (uint32_t)__cvta_generic_to_shared(sWlo) +
                         ((rb + laneAr) * KPAD + laneAk) * 2;
    const uint32_t bHb = (uint32_t)__cvta_generic_to_shared(sVhi) +
                         (laneTr * KPAD + cb + laneTd) * 2;
    const uint32_t bLb = (uint32_t)__cvta_generic_to_shared(sVlo) +
                         (laneTr * KPAD + cb + laneTd) * 2;

    const float* Ep = g_E + (size_t)b * SEQ * SEQ;
    float* Wp = outW + (size_t)b * SEQ * SEQ;
    const int g = lane >> 2, q = lane & 3;

    // staging coords: E/W tile is 64 rows x 32 float4 -> 8 per thread
    const int erow = tid >> 5;           // + i*8, i<8
    const int ec4  = (tid & 31) * 4;
    // V tile is 128 rows x 32 float4 -> 16 per thread
    const int vrow = tid >> 5;
    const int vc4  = (tid & 31) * 4;

    #pragma unroll 1
    for (int half = 0; half < 2; ++half) {
        const int it = (half == 0) ? itp : 15 - itp;
        const int i0 = it * 128;
        const int i0g = i0 + rh * 64;    // this CTA's first row

        if (tid < 64) sInv[tid] = 1.0f / g_rowsum[b * SEQ + i0g + tid];

        float acc[2][4][4];
        #pragma unroll
        for (int a = 0; a < 2; ++a)
            #pragma unroll
            for (int c = 0; c < 4; ++c)
                #pragma unroll
                for (int d = 0; d < 4; ++d) acc[a][c][d] = 0.f;

        // prefetch first E tile (8 float4/thread)
        float4 epre[8];
        #pragma unroll
        for (int i = 0; i < 8; ++i)
            epre[i] = *(const float4*)(Ep + (size_t)(i0g + erow + i * 8) * SEQ +
                                       it * 128 + ec4);
        __syncthreads();

        for (int jt = it; jt < 16; ++jt) {
            const int j0 = jt * 128;
            // stage normalized weights from prefetch regs; write W
            #pragma unroll
            for (int i = 0; i < 8; ++i) {
                int row = erow + i * 8;
                float4 v = epre[i];
                float inv = sInv[row];
                v.x *= inv; v.y *= inv; v.z *= inv; v.w *= inv;
                *(float4*)(Wp + (size_t)(i0g + row) * SEQ + j0 + ec4) = v;
                uint2 hi, lo; split4(v, hi, lo);
                *(uint2*)(sWhi + row * KPAD + ec4) = hi;
                *(uint2*)(sWlo + row * KPAD + ec4) = lo;
            }
            // stage V tile [128 j][128 d] (natural layout; ldmatrix.trans for B)
            {
                const float* Vp = V + ((size_t)b * SEQ + j0) * DIM;
                #pragma unroll
                for (int i = 0; i < 16; ++i) {
                    int row = vrow + i * 8;
                    float4 v = *(const float4*)(Vp + row * DIM + vc4);
                    uint2 hi, lo; split4(v, hi, lo);
                    *(uint2*)(sVhi + row * KPAD + vc4) = hi;
                    *(uint2*)(sVlo + row * KPAD + vc4) = lo;
                }
            }
            __syncthreads();

            // prefetch next E tile: overlaps with MMA below
            if (jt + 1 < 16) {
                #pragma unroll
                for (int i = 0; i < 8; ++i)
                    epre[i] = *(const float4*)(Ep + (size_t)(i0g + erow + i * 8) * SEQ +
                                               j0 + 128 + ec4);
            }

            #pragma unroll
            for (int ks = 0; ks < 8; ++ks) {
                uint32_t bh[8], bl[8];
                ldsm4t(bh,     bHb + ks * 16 * KPAD * 2);
                ldsm4t(bh + 4, bHb + ks * 16 * KPAD * 2 + 32);   // d-cols +16
                ldsm4t(bl,     bLb + ks * 16 * KPAD * 2);
                ldsm4t(bl + 4, bLb + ks * 16 * KPAD * 2 + 32);
                #pragma unroll
                for (int mf = 0; mf < 2; ++mf) {
                    uint32_t ah[4], al[4];
                    ldsm4(ah, aHb + mf * 16 * KPAD * 2 + ks * 32);
                    ldsm4(al, aLb + mf * 16 * KPAD * 2 + ks * 32);
                    #pragma unroll
                    for (int nf = 0; nf < 4; ++nf) {
                        mma16816(acc[mf][nf], ah, bh[2 * nf], bh[2 * nf + 1]);
                        mma16816(acc[mf][nf], ah, bl[2 * nf], bl[2 * nf + 1]);
                        mma16816(acc[mf][nf], al, bh[2 * nf], bh[2 * nf + 1]);
                    }
                }
            }
            __syncthreads();
        }

        // epilogue: write O for this CTA's 64 rows
        #pragma unroll
        for (int mf = 0; mf < 2; ++mf) {
            int r0 = i0g + rb + mf * 16 + g;
            int r1 = r0 + 8;
            #pragma unroll
            for (int nf = 0; nf < 4; ++nf) {
                int c = cb + nf * 8 + q * 2;
                *(float2*)(outO + ((size_t)b * SEQ + r0) * DIM + c) =
                    make_float2(acc[mf][nf][0], acc[mf][nf][1]);
                *(float2*)(outO + ((size_t)b * SEQ + r1) * DIM + c) =
                    make_float2(acc[mf][nf][2], acc[mf][nf][3]);
            }
        }
        __syncthreads();   // sInv/sW reuse safety for next half
    }
}

extern "C" void kernel_launch(void* const* d_in, const int* in_sizes, int n_in,
                              void* d_out, int out_size)
{
    const float* Q = (const float*)d_in[0];
    const float* K = (const float*)d_in[1];
    const float* V = (const float*)d_in[2];
    float* out  = (float*)d_out;
    float* outO = out;                               // (B,S,D)
    float* outW = out + (size_t)BATCH * SEQ * DIM;   // (B,S,S)

    static int attr_done = 0;
    if (!attr_done) {
        cudaFuncSetAttribute(scores_strip_kernel,
                             cudaFuncAttributeMaxDynamicSharedMemorySize, 139776);
        cudaFuncSetAttribute(output_kernel,
                             cudaFuncAttributeMaxDynamicSharedMemorySize, 104704);
        attr_done = 1;
    }

    scores_strip_kernel<<<dim3(8, 16), NT, 139776>>>(Q, K, outW);
    output_kernel<<<dim3(2, 8, 16), NT, 104704>>>(V, outO, outW);
}